// round 5
// baseline (speedup 1.0000x reference)
#include <cuda_runtime.h>
#include <cuda_bf16.h>
#include <math.h>

// Problem constants
#define N_HEADS 32
#define N_KV 8
#define HDIM 128
#define DIM 4096
#define BS 32
#define MAXSEQ 2048
#define KSPLIT 32
#define NSPLIT 8   // KV splits for attention

// ---------------- device scratch (static, allocation-free) ----------------
__device__ float g_qkv_part[KSPLIT][BS][6144];
__device__ float g_q[BS * 4096];
__device__ float g_knew[BS * 1024];
__device__ float g_vnew[BS * 1024];
__device__ float g_po[BS * N_HEADS * NSPLIT * HDIM];
__device__ float g_pm[BS * N_HEADS * NSPLIT];
__device__ float g_pl[BS * N_HEADS * NSPLIT];
__device__ float g_attn[BS * 4096];
__device__ float g_wo_part[KSPLIT][BS * 4096];

#define XPAD 36   // smem row pitch for GEMM xs[k][b]
#define KPITCH 129  // attention K-tile row pitch (floats), conflict-light

// packed dual-FMA: d += a * b on two fp32 lanes (one FFMA2 instruction)
__device__ __forceinline__ void fma2(unsigned long long& d,
                                     unsigned long long a,
                                     unsigned long long b) {
    asm("fma.rn.f32x2 %0, %1, %2, %0;" : "+l"(d) : "l"(a), "l"(b));
}
__device__ __forceinline__ unsigned long long bcast2(float v) {
    unsigned long long r;
    asm("mov.b64 %0, {%1, %1};" : "=l"(r) : "r"(__float_as_uint(v)));
    return r;
}
__device__ __forceinline__ float2 unpack2(unsigned long long v) {
    return *reinterpret_cast<float2*>(&v);
}

// ---------------- QKV GEMM (unchanged from R3) ---------------------------
__global__ void __launch_bounds__(128)
gemm_qkv_kernel(const float* __restrict__ x,
                const float* __restrict__ wq,
                const float* __restrict__ wk,
                const float* __restrict__ wv) {
    __shared__ float xs[128 * XPAD];
    int tid = threadIdx.x;
    int gcol = (blockIdx.x * 128 + tid) * 2;
    const float* w; int ldw, c;
    if (gcol < 4096)      { w = wq; ldw = 4096; c = gcol; }
    else if (gcol < 5120) { w = wk; ldw = 1024; c = gcol - 4096; }
    else                  { w = wv; ldw = 1024; c = gcol - 5120; }
    int kbase = blockIdx.y * 128;

    {
        const float4* x4 = (const float4*)x;
        for (int u = tid; u < 32 * 32; u += 128) {
            int b = u & 31, k4 = u >> 5;
            float4 v = x4[b * 1024 + (kbase >> 2) + k4];
            xs[(k4 * 4 + 0) * XPAD + b] = v.x;
            xs[(k4 * 4 + 1) * XPAD + b] = v.y;
            xs[(k4 * 4 + 2) * XPAD + b] = v.z;
            xs[(k4 * 4 + 3) * XPAD + b] = v.w;
        }
    }
    __syncthreads();

    unsigned long long acc0[16], acc1[16];
#pragma unroll
    for (int i = 0; i < 16; i++) { acc0[i] = 0ULL; acc1[i] = 0ULL; }

    const float* wp = w + (size_t)kbase * ldw + c;
    for (int kk = 0; kk < 128; kk += 8) {
        float2 wr[8];
#pragma unroll
        for (int j = 0; j < 8; j++)
            wr[j] = *(const float2*)(wp + (size_t)(kk + j) * ldw);
#pragma unroll
        for (int j = 0; j < 8; j++) {
            unsigned long long wx = bcast2(wr[j].x);
            unsigned long long wy = bcast2(wr[j].y);
            const float4* xrow = (const float4*)(xs + (kk + j) * XPAD);
#pragma unroll
            for (int b4 = 0; b4 < 8; b4++) {
                float4 xv = xrow[b4];
                ulonglong2 xp = *reinterpret_cast<ulonglong2*>(&xv);
                fma2(acc0[b4*2+0], wx, xp.x);
                fma2(acc0[b4*2+1], wx, xp.y);
                fma2(acc1[b4*2+0], wy, xp.x);
                fma2(acc1[b4*2+1], wy, xp.y);
            }
        }
    }
    float* out = &g_qkv_part[blockIdx.y][0][0];
#pragma unroll
    for (int i = 0; i < 16; i++) {
        float2 a0 = unpack2(acc0[i]);
        float2 a1 = unpack2(acc1[i]);
        *(float2*)&out[(2*i  ) * 6144 + gcol] = make_float2(a0.x, a1.x);
        *(float2*)&out[(2*i+1) * 6144 + gcol] = make_float2(a0.y, a1.y);
    }
}

// ---------------- reduce K-split partials + RoPE -------------------------
__global__ void rope_combine_kernel(const float* __restrict__ fc,
                                    const float* __restrict__ fs) {
    int idx = blockIdx.x * blockDim.x + threadIdx.x;
    if (idx >= 32 * 3072) return;
    int b = idx / 3072;
    int col = (idx % 3072) * 2;
    float s0 = 0.f, s1 = 0.f;
#pragma unroll
    for (int p = 0; p < KSPLIT; p++) {
        s0 += g_qkv_part[p][b][col];
        s1 += g_qkv_part[p][b][col + 1];
    }
    if (col < 4096) {
        int i = (col & 127) >> 1;
        float cc = fc[i], ss = fs[i];
        g_q[b * 4096 + col]     = s0 * cc - s1 * ss;
        g_q[b * 4096 + col + 1] = s0 * ss + s1 * cc;
    } else if (col < 5120) {
        int kc = col - 4096;
        int i = (kc & 127) >> 1;
        float cc = fc[i], ss = fs[i];
        g_knew[b * 1024 + kc]     = s0 * cc - s1 * ss;
        g_knew[b * 1024 + kc + 1] = s0 * ss + s1 * cc;
    } else {
        int vc = col - 5120;
        g_vnew[b * 1024 + vc]     = s0;
        g_vnew[b * 1024 + vc + 1] = s1;
    }
}

// ---------------- split-KV attention (smem-staged, shuffle-light) --------
// grid (8 kv-heads, 8 splits, 32 batches), block 256.
// Scores: 64-key smem tiles, thread = (key, head-pair, dim-half); packed
// f32x2 dot from smem, 2 SHFLs per key. Probs stored transposed scp[key][h].
// PV: reuse K buffer for V, packed prob-pair FFMA2.
__global__ void __launch_bounds__(256)
attn_split_kernel(const float* __restrict__ cache_k,
                  const float* __restrict__ cache_v,
                  const int* __restrict__ sp) {
    __shared__ float2 qp[2][128];          // packed q head-pairs, 2 KB
    __shared__ float kbuf[64 * KPITCH];    // 33 KB K tile (reused for V)
    __shared__ float scp[256 * 4];         // probs transposed [key][head], 4 KB
    __shared__ float sm_m[4], sm_l[4];

    int g = blockIdx.x, split = blockIdx.y, b = blockIdx.z;
    int tid = threadIdx.x;
    int L = sp ? (sp[0] + 1) : MAXSEQ;
    int chunk = (L + NSPLIT - 1) / NSPLIT;
    int t0 = split * chunk;
    int cnt = L - t0;
    if (cnt > chunk) cnt = chunk;
    if (cnt < 0) cnt = 0;

    // pack q: qp[hp][d] = (q[g*4+2hp][d], q[g*4+2hp+1][d])
    {
        int hp = tid >> 7, d = tid & 127;
        const float* gq = g_q + b * 4096 + g * 512;
        qp[hp][d] = make_float2(gq[(2 * hp) * 128 + d], gq[(2 * hp + 1) * 128 + d]);
    }

    const float scale = 0.08838834764831845f;  // 1/sqrt(128)
    int npair = (cnt + 63) >> 6;

    // ---------------- scores ----------------
    int kk   = tid >> 2;        // 0..63 key within tile
    int hp   = (tid >> 1) & 1;  // head pair
    int half = tid & 1;         // dim half
    int hd0  = half * 64;

    float4 tmp[8];
    // prefetch tile 0 (K)
    {
#pragma unroll
        for (int i = 0; i < 8; i++) {
            int u = tid + i * 256, r = u >> 5, c4 = u & 31;
            int rel = r;                       // key within tile 0
            if (rel < cnt) {
                int t = t0 + rel;
                const float4* src = (t == L - 1)
                    ? (const float4*)(g_knew + b * 1024 + g * 128)
                    : (const float4*)(cache_k + (((size_t)b * MAXSEQ + t) * N_KV + g) * HDIM);
                tmp[i] = src[c4];
            } else tmp[i] = make_float4(0.f, 0.f, 0.f, 0.f);
        }
    }
    __syncthreads();   // qp visible

    for (int p = 0; p < npair; p++) {
        // store staged tile
#pragma unroll
        for (int i = 0; i < 8; i++) {
            int u = tid + i * 256, r = u >> 5, c4 = u & 31;
            float* dst = kbuf + r * KPITCH + c4 * 4;
            dst[0] = tmp[i].x; dst[1] = tmp[i].y; dst[2] = tmp[i].z; dst[3] = tmp[i].w;
        }
        __syncthreads();
        // prefetch next tile while computing
        if (p + 1 < npair) {
#pragma unroll
            for (int i = 0; i < 8; i++) {
                int u = tid + i * 256, r = u >> 5, c4 = u & 31;
                int rel = (p + 1) * 64 + r;
                if (rel < cnt) {
                    int t = t0 + rel;
                    const float4* src = (t == L - 1)
                        ? (const float4*)(g_knew + b * 1024 + g * 128)
                        : (const float4*)(cache_k + (((size_t)b * MAXSEQ + t) * N_KV + g) * HDIM);
                    tmp[i] = src[c4];
                } else tmp[i] = make_float4(0.f, 0.f, 0.f, 0.f);
            }
        }
        // packed dot: acc = sum_d qpair[d] * k[d]
        unsigned long long acca = 0ULL, accb = 0ULL;
        const float*  krow = kbuf + kk * KPITCH + hd0;
        const float2* qrow = &qp[hp][hd0];
#pragma unroll
        for (int d = 0; d < 64; d += 2) {
            fma2(acca, *(const unsigned long long*)&qrow[d],     bcast2(krow[d]));
            fma2(accb, *(const unsigned long long*)&qrow[d + 1], bcast2(krow[d + 1]));
        }
        float2 av = unpack2(acca), bv = unpack2(accb);
        float s0 = av.x + bv.x, s1 = av.y + bv.y;
        s0 += __shfl_xor_sync(~0u, s0, 1);
        s1 += __shfl_xor_sync(~0u, s1, 1);
        if (half == 0) {
            int kg = p * 64 + kk;
            if (kg < cnt) {
                scp[kg * 4 + 2 * hp]     = s0 * scale;
                scp[kg * 4 + 2 * hp + 1] = s1 * scale;
            }
        }
        __syncthreads();
    }

    // ---------------- softmax (4 warps, one per head) ----------------
    if (tid < 128) {
        int h = tid >> 5, l = tid & 31;
        float m = -1e30f;
        for (int ti = l; ti < cnt; ti += 32) m = fmaxf(m, scp[ti * 4 + h]);
#pragma unroll
        for (int off = 16; off; off >>= 1) m = fmaxf(m, __shfl_xor_sync(~0u, m, off));
        float lsum = 0.f;
        for (int ti = l; ti < cnt; ti += 32) {
            float e = __expf(scp[ti * 4 + h] - m);
            scp[ti * 4 + h] = e;
            lsum += e;
        }
#pragma unroll
        for (int off = 16; off; off >>= 1) lsum += __shfl_xor_sync(~0u, lsum, off);
        if (l == 0) { sm_m[h] = m; sm_l[h] = lsum; }
    }
    __syncthreads();

    // ---------------- PV (reuse kbuf for V, pitch 128) ----------------
    int dd  = tid & 127;
    int hp2 = tid >> 7;        // head pair (2hp2, 2hp2+1)
    float4* vbuf4 = (float4*)kbuf;

    // prefetch V tile 0
#pragma unroll
    for (int i = 0; i < 8; i++) {
        int u = tid + i * 256, r = u >> 5, c4 = u & 31;
        if (r < cnt) {
            int t = t0 + r;
            const float4* src = (t == L - 1)
                ? (const float4*)(g_vnew + b * 1024 + g * 128)
                : (const float4*)(cache_v + (((size_t)b * MAXSEQ + t) * N_KV + g) * HDIM);
            tmp[i] = src[c4];
        } else tmp[i] = make_float4(0.f, 0.f, 0.f, 0.f);
    }

    unsigned long long acc0 = 0ULL, acc1 = 0ULL;
    for (int p = 0; p < npair; p++) {
        __syncthreads();   // previous tile consumed (and scp ready on p=0)
#pragma unroll
        for (int i = 0; i < 8; i++) {
            int u = tid + i * 256;
            vbuf4[u] = tmp[i];   // STS.128, pitch 128
        }
        __syncthreads();
        if (p + 1 < npair) {
#pragma unroll
            for (int i = 0; i < 8; i++) {
                int u = tid + i * 256, r = u >> 5, c4 = u & 31;
                int rel = (p + 1) * 64 + r;
                if (rel < cnt) {
                    int t = t0 + rel;
                    const float4* src = (t == L - 1)
                        ? (const float4*)(g_vnew + b * 1024 + g * 128)
                        : (const float4*)(cache_v + (((size_t)b * MAXSEQ + t) * N_KV + g) * HDIM);
                    tmp[i] = src[c4];
                } else tmp[i] = make_float4(0.f, 0.f, 0.f, 0.f);
            }
        }
        int nt = cnt - p * 64; if (nt > 64) nt = 64;
        int base = p * 64;
        int j = 0;
        for (; j + 1 < nt; j += 2) {
            fma2(acc0, *(const unsigned long long*)&scp[(base + j)     * 4 + 2 * hp2],
                 bcast2(kbuf[j * 128 + dd]));
            fma2(acc1, *(const unsigned long long*)&scp[(base + j + 1) * 4 + 2 * hp2],
                 bcast2(kbuf[(j + 1) * 128 + dd]));
        }
        if (j < nt) {
            fma2(acc0, *(const unsigned long long*)&scp[(base + j) * 4 + 2 * hp2],
                 bcast2(kbuf[j * 128 + dd]));
        }
    }

    float2 o0 = unpack2(acc0), o1 = unpack2(acc1);
    float oa = o0.x + o1.x, ob = o0.y + o1.y;
    int ha = g * 4 + 2 * hp2, hb = ha + 1;
    g_po[((b * N_HEADS + ha) * NSPLIT + split) * HDIM + dd] = oa;
    g_po[((b * N_HEADS + hb) * NSPLIT + split) * HDIM + dd] = ob;
    if (dd == 0) {
        g_pm[(b * N_HEADS + ha) * NSPLIT + split] = sm_m[2 * hp2];
        g_pl[(b * N_HEADS + ha) * NSPLIT + split] = sm_l[2 * hp2];
        g_pm[(b * N_HEADS + hb) * NSPLIT + split] = sm_m[2 * hp2 + 1];
        g_pl[(b * N_HEADS + hb) * NSPLIT + split] = sm_l[2 * hp2 + 1];
    }
}

// ---------------- combine attention splits (log-sum-exp) -----------------
__global__ void combine_attn_kernel() {
    int h = blockIdx.x, b = blockIdx.y, d = threadIdx.x;
    int base = (b * N_HEADS + h) * NSPLIT;
    float M = -1e30f;
#pragma unroll
    for (int s = 0; s < NSPLIT; s++) M = fmaxf(M, g_pm[base + s]);
    float denom = 0.f, o = 0.f;
#pragma unroll
    for (int s = 0; s < NSPLIT; s++) {
        float wgt = __expf(g_pm[base + s] - M);
        denom += wgt * g_pl[base + s];
        o     += wgt * g_po[(base + s) * HDIM + d];
    }
    g_attn[b * 4096 + h * HDIM + d] = o / denom;
}

// ---------------- WO GEMM (unchanged from R3) ----------------------------
__global__ void __launch_bounds__(128)
gemm_wo_kernel(const float* __restrict__ wo) {
    __shared__ float xs[128 * XPAD];
    int tid = threadIdx.x;
    int c = (blockIdx.x * 128 + tid) * 2;
    int kbase = blockIdx.y * 128;

    {
        const float4* x4 = (const float4*)g_attn;
        for (int u = tid; u < 32 * 32; u += 128) {
            int b = u & 31, k4 = u >> 5;
            float4 v = x4[b * 1024 + (kbase >> 2) + k4];
            xs[(k4 * 4 + 0) * XPAD + b] = v.x;
            xs[(k4 * 4 + 1) * XPAD + b] = v.y;
            xs[(k4 * 4 + 2) * XPAD + b] = v.z;
            xs[(k4 * 4 + 3) * XPAD + b] = v.w;
        }
    }
    __syncthreads();

    unsigned long long acc0[16], acc1[16];
#pragma unroll
    for (int i = 0; i < 16; i++) { acc0[i] = 0ULL; acc1[i] = 0ULL; }

    const float* wp = wo + (size_t)kbase * 4096 + c;
    for (int kk = 0; kk < 128; kk += 8) {
        float2 wr[8];
#pragma unroll
        for (int j = 0; j < 8; j++)
            wr[j] = *(const float2*)(wp + (size_t)(kk + j) * 4096);
#pragma unroll
        for (int j = 0; j < 8; j++) {
            unsigned long long wx = bcast2(wr[j].x);
            unsigned long long wy = bcast2(wr[j].y);
            const float4* xrow = (const float4*)(xs + (kk + j) * XPAD);
#pragma unroll
            for (int b4 = 0; b4 < 8; b4++) {
                float4 xv = xrow[b4];
                ulonglong2 xp = *reinterpret_cast<ulonglong2*>(&xv);
                fma2(acc0[b4*2+0], wx, xp.x);
                fma2(acc0[b4*2+1], wx, xp.y);
                fma2(acc1[b4*2+0], wy, xp.x);
                fma2(acc1[b4*2+1], wy, xp.y);
            }
        }
    }
    float* out = g_wo_part[blockIdx.y];
#pragma unroll
    for (int i = 0; i < 16; i++) {
        float2 a0 = unpack2(acc0[i]);
        float2 a1 = unpack2(acc1[i]);
        *(float2*)&out[(2*i  ) * 4096 + c] = make_float2(a0.x, a1.x);
        *(float2*)&out[(2*i+1) * 4096 + c] = make_float2(a0.y, a1.y);
    }
}

// ---------------- sum WO partials into d_out -----------------------------
__global__ void final_sum_kernel(float* __restrict__ out) {
    int idx = blockIdx.x * blockDim.x + threadIdx.x;
    float s = 0.f;
#pragma unroll
    for (int p = 0; p < KSPLIT; p++) s += g_wo_part[p][idx];
    out[idx] = s;
}

// ---------------- launch -------------------------------------------------
extern "C" void kernel_launch(void* const* d_in, const int* in_sizes, int n_in,
                              void* d_out, int out_size) {
    const float* x  = (const float*)d_in[0];
    const float* wq = (const float*)d_in[1];
    const float* wk = (const float*)d_in[2];
    const float* wv = (const float*)d_in[3];
    const float* wo = (const float*)d_in[4];
    const float* ck = (const float*)d_in[5];
    const float* cv = (const float*)d_in[6];
    const float* fc = (const float*)d_in[7];
    const float* fs = (const float*)d_in[8];
    const int*   sp = (n_in > 9) ? (const int*)d_in[9] : nullptr;

    gemm_qkv_kernel<<<dim3(24, KSPLIT), 128>>>(x, wq, wk, wv);
    rope_combine_kernel<<<384, 256>>>(fc, fs);
    attn_split_kernel<<<dim3(N_KV, NSPLIT, BS), 256>>>(ck, cv, sp);
    combine_attn_kernel<<<dim3(N_HEADS, BS), 128>>>();
    gemm_wo_kernel<<<dim3(16, KSPLIT), 128>>>(wo);
    final_sum_kernel<<<512, 256>>>((float*)d_out);
}

// round 6
// speedup vs baseline: 2.5491x; 2.5491x over previous
#include <cuda_runtime.h>
#include <cuda_bf16.h>
#include <math.h>

// Problem constants
#define N_HEADS 32
#define N_KV 8
#define HDIM 128
#define DIM 4096
#define BS 32
#define MAXSEQ 2048
#define KSPLIT 32
#define NSPLIT 8   // KV splits for attention

// ---------------- device scratch (static, allocation-free) ----------------
__device__ float g_qkv_part[KSPLIT][BS][6144];
__device__ float g_q[BS * 4096];
__device__ float g_knew[BS * 1024];
__device__ float g_vnew[BS * 1024];
__device__ float g_po[BS * N_HEADS * NSPLIT * HDIM];
__device__ float g_pm[BS * N_HEADS * NSPLIT];
__device__ float g_pl[BS * N_HEADS * NSPLIT];
__device__ float g_attn[BS * 4096];
__device__ float g_wo_part[KSPLIT][BS * 4096];

#define XPAD 36   // smem row pitch for xs[k][b]

// packed dual-FMA: d += a * b on two fp32 lanes (one FFMA2 instruction)
__device__ __forceinline__ void fma2(unsigned long long& d,
                                     unsigned long long a,
                                     unsigned long long b) {
    asm("fma.rn.f32x2 %0, %1, %2, %0;" : "+l"(d) : "l"(a), "l"(b));
}
__device__ __forceinline__ unsigned long long bcast2(float v) {
    unsigned long long r;
    asm("mov.b64 %0, {%1, %1};" : "=l"(r) : "r"(__float_as_uint(v)));
    return r;
}
__device__ __forceinline__ float2 unpack2(unsigned long long v) {
    return *reinterpret_cast<float2*>(&v);
}

// ---------------- QKV GEMM: [32,4096] @ concat(wq,wk,wv) -> partials -----
__global__ void __launch_bounds__(128)
gemm_qkv_kernel(const float* __restrict__ x,
                const float* __restrict__ wq,
                const float* __restrict__ wk,
                const float* __restrict__ wv) {
    __shared__ float xs[128 * XPAD];
    int tid = threadIdx.x;
    int gcol = (blockIdx.x * 128 + tid) * 2;
    const float* w; int ldw, c;
    if (gcol < 4096)      { w = wq; ldw = 4096; c = gcol; }
    else if (gcol < 5120) { w = wk; ldw = 1024; c = gcol - 4096; }
    else                  { w = wv; ldw = 1024; c = gcol - 5120; }
    int kbase = blockIdx.y * 128;

    {
        const float4* x4 = (const float4*)x;
        for (int u = tid; u < 32 * 32; u += 128) {
            int b = u & 31, k4 = u >> 5;
            float4 v = x4[b * 1024 + (kbase >> 2) + k4];
            xs[(k4 * 4 + 0) * XPAD + b] = v.x;
            xs[(k4 * 4 + 1) * XPAD + b] = v.y;
            xs[(k4 * 4 + 2) * XPAD + b] = v.z;
            xs[(k4 * 4 + 3) * XPAD + b] = v.w;
        }
    }
    __syncthreads();

    unsigned long long acc0[16], acc1[16];
#pragma unroll
    for (int i = 0; i < 16; i++) { acc0[i] = 0ULL; acc1[i] = 0ULL; }

    const float* wp = w + (size_t)kbase * ldw + c;
    for (int kk = 0; kk < 128; kk += 8) {
        float2 wr[8];
#pragma unroll
        for (int j = 0; j < 8; j++)
            wr[j] = *(const float2*)(wp + (size_t)(kk + j) * ldw);
#pragma unroll
        for (int j = 0; j < 8; j++) {
            unsigned long long wx = bcast2(wr[j].x);
            unsigned long long wy = bcast2(wr[j].y);
            const float4* xrow = (const float4*)(xs + (kk + j) * XPAD);
#pragma unroll
            for (int b4 = 0; b4 < 8; b4++) {
                float4 xv = xrow[b4];
                ulonglong2 xp = *reinterpret_cast<ulonglong2*>(&xv);
                fma2(acc0[b4*2+0], wx, xp.x);
                fma2(acc0[b4*2+1], wx, xp.y);
                fma2(acc1[b4*2+0], wy, xp.x);
                fma2(acc1[b4*2+1], wy, xp.y);
            }
        }
    }
    float* out = &g_qkv_part[blockIdx.y][0][0];
#pragma unroll
    for (int i = 0; i < 16; i++) {
        float2 a0 = unpack2(acc0[i]);
        float2 a1 = unpack2(acc1[i]);
        *(float2*)&out[(2*i  ) * 6144 + gcol] = make_float2(a0.x, a1.x);
        *(float2*)&out[(2*i+1) * 6144 + gcol] = make_float2(a0.y, a1.y);
    }
}

// ---------------- reduce K-split partials + RoPE -------------------------
__global__ void rope_combine_kernel(const float* __restrict__ fc,
                                    const float* __restrict__ fs) {
    int idx = blockIdx.x * blockDim.x + threadIdx.x;
    if (idx >= 32 * 3072) return;
    int b = idx / 3072;
    int col = (idx % 3072) * 2;
    float s0 = 0.f, s1 = 0.f;
#pragma unroll
    for (int p = 0; p < KSPLIT; p++) {
        s0 += g_qkv_part[p][b][col];
        s1 += g_qkv_part[p][b][col + 1];
    }
    if (col < 4096) {
        int i = (col & 127) >> 1;
        float cc = fc[i], ss = fs[i];
        g_q[b * 4096 + col]     = s0 * cc - s1 * ss;
        g_q[b * 4096 + col + 1] = s0 * ss + s1 * cc;
    } else if (col < 5120) {
        int kc = col - 4096;
        int i = (kc & 127) >> 1;
        float cc = fc[i], ss = fs[i];
        g_knew[b * 1024 + kc]     = s0 * cc - s1 * ss;
        g_knew[b * 1024 + kc + 1] = s0 * ss + s1 * cc;
    } else {
        int vc = col - 5120;
        g_vnew[b * 1024 + vc]     = s0;
        g_vnew[b * 1024 + vc + 1] = s1;
    }
}

// ---------------- split-KV attention (R3 structure, dual-key score) ------
// grid (8 kv-heads, 8 splits, 32 batches), block 256 (8 warps).
__global__ void __launch_bounds__(256)
attn_split_kernel(const float* __restrict__ cache_k,
                  const float* __restrict__ cache_v,
                  const int* __restrict__ sp) {
    __shared__ float qs[4 * 128];
    __shared__ float sc[4][256];
    __shared__ float vt[32 * 128];
    __shared__ float sm_m[4], sm_l[4];

    int g = blockIdx.x, split = blockIdx.y, b = blockIdx.z;
    int tid = threadIdx.x, lane = tid & 31, w = tid >> 5;
    int L = sp ? (sp[0] + 1) : MAXSEQ;
    int chunk = (L + NSPLIT - 1) / NSPLIT;
    int t0 = split * chunk;
    int cnt = L - t0;
    if (cnt > chunk) cnt = chunk;
    if (cnt < 0) cnt = 0;

    for (int u = tid; u < 512; u += 256)
        qs[u] = g_q[b * 4096 + g * 512 + u];
    __syncthreads();

    float4 qr[4];
#pragma unroll
    for (int h = 0; h < 4; h++) qr[h] = ((const float4*)qs)[h * 32 + lane];

    const float scale = 0.08838834764831845f;

    // ---- scores: 2 keys per warp iteration (front-batched LDG.128 x2,
    //      interleaved shuffle-reduction chains) ----
    for (int ti = w * 2; ti < cnt; ti += 16) {
        int t = t0 + ti;
        bool has2 = (ti + 1) < cnt;
        const float4* kp0 = (t == L - 1)
            ? (const float4*)(g_knew + b * 1024 + g * 128)
            : (const float4*)(cache_k + (((size_t)b * MAXSEQ + t) * N_KV + g) * HDIM);
        const float4* kp1 = (t + 1 == L - 1)
            ? (const float4*)(g_knew + b * 1024 + g * 128)
            : (const float4*)(cache_k + (((size_t)b * MAXSEQ + t + 1) * N_KV + g) * HDIM);
        float4 kv0 = kp0[lane];
        float4 kv1 = has2 ? kp1[lane] : make_float4(0.f, 0.f, 0.f, 0.f);

        float a0 = qr[0].x*kv0.x + qr[0].y*kv0.y + qr[0].z*kv0.z + qr[0].w*kv0.w;
        float a1 = qr[1].x*kv0.x + qr[1].y*kv0.y + qr[1].z*kv0.z + qr[1].w*kv0.w;
        float a2 = qr[2].x*kv0.x + qr[2].y*kv0.y + qr[2].z*kv0.z + qr[2].w*kv0.w;
        float a3 = qr[3].x*kv0.x + qr[3].y*kv0.y + qr[3].z*kv0.z + qr[3].w*kv0.w;
        float b0 = qr[0].x*kv1.x + qr[0].y*kv1.y + qr[0].z*kv1.z + qr[0].w*kv1.w;
        float b1 = qr[1].x*kv1.x + qr[1].y*kv1.y + qr[1].z*kv1.z + qr[1].w*kv1.w;
        float b2 = qr[2].x*kv1.x + qr[2].y*kv1.y + qr[2].z*kv1.z + qr[2].w*kv1.w;
        float b3 = qr[3].x*kv1.x + qr[3].y*kv1.y + qr[3].z*kv1.z + qr[3].w*kv1.w;
#pragma unroll
        for (int off = 16; off; off >>= 1) {
            a0 += __shfl_xor_sync(~0u, a0, off);
            b0 += __shfl_xor_sync(~0u, b0, off);
            a1 += __shfl_xor_sync(~0u, a1, off);
            b1 += __shfl_xor_sync(~0u, b1, off);
            a2 += __shfl_xor_sync(~0u, a2, off);
            b2 += __shfl_xor_sync(~0u, b2, off);
            a3 += __shfl_xor_sync(~0u, a3, off);
            b3 += __shfl_xor_sync(~0u, b3, off);
        }
        if (lane == 0) {
            sc[0][ti] = a0 * scale; sc[1][ti] = a1 * scale;
            sc[2][ti] = a2 * scale; sc[3][ti] = a3 * scale;
            if (has2) {
                sc[0][ti+1] = b0 * scale; sc[1][ti+1] = b1 * scale;
                sc[2][ti+1] = b2 * scale; sc[3][ti+1] = b3 * scale;
            }
        }
    }
    __syncthreads();

    // ---- softmax stats (one warp per head) ----
    if (w < 4) {
        float m = -1e30f;
        for (int ti = lane; ti < cnt; ti += 32) m = fmaxf(m, sc[w][ti]);
#pragma unroll
        for (int off = 16; off; off >>= 1) m = fmaxf(m, __shfl_xor_sync(~0u, m, off));
        float l = 0.f;
        for (int ti = lane; ti < cnt; ti += 32) {
            float e = __expf(sc[w][ti] - m);
            sc[w][ti] = e;
            l += e;
        }
#pragma unroll
        for (int off = 16; off; off >>= 1) l += __shfl_xor_sync(~0u, l, off);
        if (lane == 0) { sm_m[w] = m; sm_l[w] = l; }
    }
    __syncthreads();

    // ---- PV: smem-tiled V (R3 structure) ----
    int h0 = tid >> 7;
    int d0 = tid & 127;
    int h1 = h0 + 2;
    float acc0 = 0.f, acc1 = 0.f;
    for (int tb = 0; tb < cnt; tb += 32) {
        int nt = cnt - tb; if (nt > 32) nt = 32;
        for (int u = tid; u < nt * 32; u += 256) {
            int r = u >> 5, c4 = u & 31;
            int t = t0 + tb + r;
            const float4* vp = (t == L - 1)
                ? (const float4*)(g_vnew + b * 1024 + g * 128)
                : (const float4*)(cache_v + (((size_t)b * MAXSEQ + t) * N_KV + g) * HDIM);
            ((float4*)vt)[r * 32 + c4] = vp[c4];
        }
        __syncthreads();
        for (int j = 0; j < nt; j++) {
            float vv = vt[j * 128 + d0];
            acc0 = fmaf(sc[h0][tb + j], vv, acc0);
            acc1 = fmaf(sc[h1][tb + j], vv, acc1);
        }
        __syncthreads();
    }

    int hh0 = g * 4 + h0, hh1 = g * 4 + h1;
    g_po[((b * N_HEADS + hh0) * NSPLIT + split) * HDIM + d0] = acc0;
    g_po[((b * N_HEADS + hh1) * NSPLIT + split) * HDIM + d0] = acc1;
    if (d0 == 0) {
        g_pm[(b * N_HEADS + hh0) * NSPLIT + split] = sm_m[h0];
        g_pl[(b * N_HEADS + hh0) * NSPLIT + split] = sm_l[h0];
        g_pm[(b * N_HEADS + hh1) * NSPLIT + split] = sm_m[h1];
        g_pl[(b * N_HEADS + hh1) * NSPLIT + split] = sm_l[h1];
    }
}

// ---------------- combine attention splits (log-sum-exp) -----------------
__global__ void combine_attn_kernel() {
    int h = blockIdx.x, b = blockIdx.y, d = threadIdx.x;
    int base = (b * N_HEADS + h) * NSPLIT;
    float M = -1e30f;
#pragma unroll
    for (int s = 0; s < NSPLIT; s++) M = fmaxf(M, g_pm[base + s]);
    float denom = 0.f, o = 0.f;
#pragma unroll
    for (int s = 0; s < NSPLIT; s++) {
        float wgt = __expf(g_pm[base + s] - M);
        denom += wgt * g_pl[base + s];
        o     += wgt * g_po[(base + s) * HDIM + d];
    }
    g_attn[b * 4096 + h * HDIM + d] = o / denom;
}

// ---------------- WO GEMM: g_attn[32,4096] @ wo[4096,4096] ---------------
__global__ void __launch_bounds__(128)
gemm_wo_kernel(const float* __restrict__ wo) {
    __shared__ float xs[128 * XPAD];
    int tid = threadIdx.x;
    int c = (blockIdx.x * 128 + tid) * 2;
    int kbase = blockIdx.y * 128;

    {
        const float4* x4 = (const float4*)g_attn;
        for (int u = tid; u < 32 * 32; u += 128) {
            int b = u & 31, k4 = u >> 5;
            float4 v = x4[b * 1024 + (kbase >> 2) + k4];
            xs[(k4 * 4 + 0) * XPAD + b] = v.x;
            xs[(k4 * 4 + 1) * XPAD + b] = v.y;
            xs[(k4 * 4 + 2) * XPAD + b] = v.z;
            xs[(k4 * 4 + 3) * XPAD + b] = v.w;
        }
    }
    __syncthreads();

    unsigned long long acc0[16], acc1[16];
#pragma unroll
    for (int i = 0; i < 16; i++) { acc0[i] = 0ULL; acc1[i] = 0ULL; }

    const float* wp = wo + (size_t)kbase * 4096 + c;
    for (int kk = 0; kk < 128; kk += 8) {
        float2 wr[8];
#pragma unroll
        for (int j = 0; j < 8; j++)
            wr[j] = *(const float2*)(wp + (size_t)(kk + j) * 4096);
#pragma unroll
        for (int j = 0; j < 8; j++) {
            unsigned long long wx = bcast2(wr[j].x);
            unsigned long long wy = bcast2(wr[j].y);
            const float4* xrow = (const float4*)(xs + (kk + j) * XPAD);
#pragma unroll
            for (int b4 = 0; b4 < 8; b4++) {
                float4 xv = xrow[b4];
                ulonglong2 xp = *reinterpret_cast<ulonglong2*>(&xv);
                fma2(acc0[b4*2+0], wx, xp.x);
                fma2(acc0[b4*2+1], wx, xp.y);
                fma2(acc1[b4*2+0], wy, xp.x);
                fma2(acc1[b4*2+1], wy, xp.y);
            }
        }
    }
    float* out = g_wo_part[blockIdx.y];
#pragma unroll
    for (int i = 0; i < 16; i++) {
        float2 a0 = unpack2(acc0[i]);
        float2 a1 = unpack2(acc1[i]);
        *(float2*)&out[(2*i  ) * 4096 + c] = make_float2(a0.x, a1.x);
        *(float2*)&out[(2*i+1) * 4096 + c] = make_float2(a0.y, a1.y);
    }
}

// ---------------- sum WO partials into d_out -----------------------------
__global__ void final_sum_kernel(float* __restrict__ out) {
    int idx = blockIdx.x * blockDim.x + threadIdx.x;
    float s = 0.f;
#pragma unroll
    for (int p = 0; p < KSPLIT; p++) s += g_wo_part[p][idx];
    out[idx] = s;
}

// ---------------- launch -------------------------------------------------
extern "C" void kernel_launch(void* const* d_in, const int* in_sizes, int n_in,
                              void* d_out, int out_size) {
    const float* x  = (const float*)d_in[0];
    const float* wq = (const float*)d_in[1];
    const float* wk = (const float*)d_in[2];
    const float* wv = (const float*)d_in[3];
    const float* wo = (const float*)d_in[4];
    const float* ck = (const float*)d_in[5];
    const float* cv = (const float*)d_in[6];
    const float* fc = (const float*)d_in[7];
    const float* fs = (const float*)d_in[8];
    const int*   sp = (n_in > 9) ? (const int*)d_in[9] : nullptr;

    gemm_qkv_kernel<<<dim3(24, KSPLIT), 128>>>(x, wq, wk, wv);
    rope_combine_kernel<<<384, 256>>>(fc, fs);
    attn_split_kernel<<<dim3(N_KV, NSPLIT, BS), 256>>>(ck, cv, sp);
    combine_attn_kernel<<<dim3(N_HEADS, BS), 128>>>();
    gemm_wo_kernel<<<dim3(16, KSPLIT), 128>>>(wo);
    final_sum_kernel<<<512, 256>>>((float*)d_out);
}